// round 1
// baseline (speedup 1.0000x reference)
#include <cuda_runtime.h>

#define SB 4096
#define BB 8
#define DD 1024
#define NN 256

// scratch (device globals — no allocation allowed)
__device__ float g_xmean[BB * SB];
__device__ float g_ys[BB * SB];

// ---------------------------------------------------------------------------
// Kernel 1: x_mean[b,s] = mean over D of x[b,s,:]   (one warp per row)
// ---------------------------------------------------------------------------
__global__ void __launch_bounds__(256) mean_kernel(const float* __restrict__ x) {
    int gw   = (blockIdx.x * 256 + threadIdx.x) >> 5;   // global warp = row id
    int lane = threadIdx.x & 31;
    const float4* xr = reinterpret_cast<const float4*>(x) + (size_t)gw * (DD / 4);
    float s = 0.f;
#pragma unroll
    for (int i = 0; i < 8; ++i) {
        float4 v = xr[i * 32 + lane];
        s += (v.x + v.y) + (v.z + v.w);
    }
#pragma unroll
    for (int o = 16; o > 0; o >>= 1) s += __shfl_xor_sync(0xffffffffu, s, o);
    if (lane == 0) g_xmean[gw] = s * (1.0f / DD);
}

// ---------------------------------------------------------------------------
// Kernel 2: sequential scan. One warp per batch, 8 states per lane.
// Recurrence: h' = a*h + bd*xm_t ; h = LN(h')*1/(1+gate*vol_t) ; ys = <h,c>
// Off-critical-path work (next-step bd*xm, 1/(1+g*vol), ys reduction, loads)
// is software-pipelined into the shuffle-reduction latency window.
// ---------------------------------------------------------------------------
__global__ void __launch_bounds__(32) scan_kernel(
    const float* __restrict__ vol,      // [B,S]
    const float* __restrict__ llr,      // [N] log_lambda_real
    const float* __restrict__ logb,     // [N]
    const float* __restrict__ cvec,     // [N]
    const float* __restrict__ logstep,  // [1]
    const float* __restrict__ vgate,    // [N]
    const float* __restrict__ lnw,      // [N]
    const float* __restrict__ lnb)      // [N]
{
    const int b    = blockIdx.x;
    const int lane = threadIdx.x;
    const float step = expf(logstep[0]);

    float a_[8], bd_[8], w_[8], be_[8], g_[8], c_[8], h_[8];
#pragma unroll
    for (int k = 0; k < 8; ++k) {
        int n = k * 32 + lane;
        float lam = -expf(llr[n]);
        float ad  = (2.f + step * lam) / (2.f - step * lam);
        a_[k]  = ad;
        bd_[k] = 0.5f * step * (1.f + ad) * expf(logb[n]);
        w_[k]  = lnw[n];
        be_[k] = lnb[n];
        g_[k]  = 1.f / (1.f + expf(-vgate[n]));
        c_[k]  = cvec[n];
        h_[k]  = 0.f;
    }

    const float* __restrict__ xmb = g_xmean + b * SB;
    const float* __restrict__ vlb = vol + b * SB;
    float* __restrict__ ysb = g_ys + b * SB;

    // 2-deep scalar prefetch pipeline (xm/vol are L2-resident, uniform loads)
    float xm_n = xmb[1], vl_n = vlb[1];
    float xm_c = xmb[0], vl_c = vlb[0];

    // step-0 per-element aux
    float bdx[8], sv[8];
#pragma unroll
    for (int k = 0; k < 8; ++k) {
        bdx[k] = bd_[k] * xm_c;
        sv[k]  = __fdividef(1.f, fmaf(g_[k], vl_c, 1.f));
    }

    for (int t = 0; t < SB; ++t) {
        // prefetch t+2 (issued immediately; lands well before needed)
        float xm_p = 0.f, vl_p = 0.f;
        if (t + 2 < SB) { xm_p = xmb[t + 2]; vl_p = vlb[t + 2]; }

        // ---- critical path start: h' ----
        float hp[8];
#pragma unroll
        for (int k = 0; k < 8; ++k) hp[k] = fmaf(a_[k], h_[k], bdx[k]);

        // local tree for sum and sum-of-squares (var = E[h^2]-mu^2, one pass)
        float s = ((hp[0] + hp[1]) + (hp[2] + hp[3])) + ((hp[4] + hp[5]) + (hp[6] + hp[7]));
        float q01 = fmaf(hp[0], hp[0], hp[1] * hp[1]);
        float q23 = fmaf(hp[2], hp[2], hp[3] * hp[3]);
        float q45 = fmaf(hp[4], hp[4], hp[5] * hp[5]);
        float q67 = fmaf(hp[6], hp[6], hp[7] * hp[7]);
        float q = (q01 + q23) + (q45 + q67);

        // butterfly reduction (5 levels, s & q pipelined per level)
#pragma unroll
        for (int o = 16; o > 0; o >>= 1) {
            s += __shfl_xor_sync(0xffffffffu, s, o);
            q += __shfl_xor_sync(0xffffffffu, q, o);
        }

        // independent work for step t+1, overlaps the SHFL latency above
        float bdxn[8], svn[8];
#pragma unroll
        for (int k = 0; k < 8; ++k) {
            bdxn[k] = bd_[k] * xm_n;
            svn[k]  = __fdividef(1.f, fmaf(g_[k], vl_n, 1.f));
        }

        float mu  = s * (1.f / NN);
        float var = fmaf(q, 1.f / NN, -mu * mu);
        float rs  = rsqrtf(var + 1e-5f);
        float nmr = -mu * rs;

        // normalize + affine + gate + output projection partial
        float p = 0.f;
#pragma unroll
        for (int k = 0; k < 8; ++k) {
            float hn = fmaf(fmaf(hp[k], rs, nmr), w_[k], be_[k]);
            float hg = hn * sv[k];
            h_[k] = hg;                       // <- carried state (critical path end)
            p = fmaf(hg, c_[k], p);           // off-path (only feeds the store)
        }
        // ys reduction: off critical path, overlaps next iteration's chain
#pragma unroll
        for (int o = 16; o > 0; o >>= 1) p += __shfl_xor_sync(0xffffffffu, p, o);
        if (lane == 0) ysb[t] = p;

        // rotate pipelines
#pragma unroll
        for (int k = 0; k < 8; ++k) { bdx[k] = bdxn[k]; sv[k] = svn[k]; }
        xm_c = xm_n; vl_c = vl_n; xm_n = xm_p; vl_n = vl_p;
    }
}

// ---------------------------------------------------------------------------
// Kernel 3: out = (A + (1-A)*d) * x + (1-A) * ys[b,s]     (float4 vectorized)
// ---------------------------------------------------------------------------
__global__ void __launch_bounds__(256) out_kernel(
    const float* __restrict__ x, float* __restrict__ out,
    const float* __restrict__ log_d, const float* __restrict__ alpha)
{
    int i = blockIdx.x * 256 + threadIdx.x;             // float4 index
    float A  = 1.f / (1.f + expf(-alpha[0]));
    float cx = A + (1.f - A) * expf(log_d[0]);
    float cy = 1.f - A;
    float add = cy * g_ys[i >> 8];                      // 256 float4 per (b,s) row
    float4 v = reinterpret_cast<const float4*>(x)[i];
    v.x = fmaf(cx, v.x, add);
    v.y = fmaf(cx, v.y, add);
    v.z = fmaf(cx, v.z, add);
    v.w = fmaf(cx, v.w, add);
    reinterpret_cast<float4*>(out)[i] = v;
}

// ---------------------------------------------------------------------------
extern "C" void kernel_launch(void* const* d_in, const int* in_sizes, int n_in,
                              void* d_out, int out_size) {
    const float* x    = (const float*)d_in[0];   // [B,S,D]
    const float* vol  = (const float*)d_in[1];   // [B,S,1]
    const float* llr  = (const float*)d_in[2];   // [N]
    const float* logb = (const float*)d_in[3];   // [N,1]
    const float* cvec = (const float*)d_in[4];   // [1,N]
    const float* logd = (const float*)d_in[5];   // [1]
    const float* lstp = (const float*)d_in[6];   // [1]
    const float* vg   = (const float*)d_in[7];   // [N]
    const float* alp  = (const float*)d_in[8];   // [1]
    const float* lnw  = (const float*)d_in[9];   // [N]
    const float* lnb  = (const float*)d_in[10];  // [N]
    float* out = (float*)d_out;

    mean_kernel<<<(BB * SB) / 8, 256>>>(x);                       // 32768 warps
    scan_kernel<<<BB, 32>>>(vol, llr, logb, cvec, lstp, vg, lnw, lnb);
    out_kernel<<<(BB * SB * DD) / 1024, 256>>>(x, out, logd, alp); // float4 grid
}

// round 4
// speedup vs baseline: 1.5929x; 1.5929x over previous
#include <cuda_runtime.h>

#define SB 4096
#define BB 8
#define DD 1024
#define NN 256

// scratch (device globals — no allocation allowed)
__device__ float g_xmean[BB * SB];
__device__ float g_part[BB * SB * 32];   // per-lane ys partials (reduced later)
__device__ float g_ys[BB * SB];

typedef unsigned long long u64;

// ---- packed f32x2 helpers (Blackwell FFMA2/FMUL2/FADD2) ----
__device__ __forceinline__ u64 pk2(float lo, float hi) {
    u64 r; asm("mov.b64 %0,{%1,%2};" : "=l"(r) : "f"(lo), "f"(hi)); return r;
}
__device__ __forceinline__ void upk2(u64 v, float& lo, float& hi) {
    asm("mov.b64 {%0,%1},%2;" : "=f"(lo), "=f"(hi) : "l"(v));
}
__device__ __forceinline__ u64 f2fma(u64 a, u64 b, u64 c) {
    u64 d; asm("fma.rn.f32x2 %0,%1,%2,%3;" : "=l"(d) : "l"(a), "l"(b), "l"(c)); return d;
}
__device__ __forceinline__ u64 f2mul(u64 a, u64 b) {
    u64 d; asm("mul.rn.f32x2 %0,%1,%2;" : "=l"(d) : "l"(a), "l"(b)); return d;
}
__device__ __forceinline__ u64 f2add(u64 a, u64 b) {
    u64 d; asm("add.rn.f32x2 %0,%1,%2;" : "=l"(d) : "l"(a), "l"(b)); return d;
}
__device__ __forceinline__ float frcp(float x) {
    float r; asm("rcp.approx.f32 %0,%1;" : "=f"(r) : "f"(x)); return r;
}
__device__ __forceinline__ float frsq(float x) {
    float r; asm("rsqrt.approx.f32 %0,%1;" : "=f"(r) : "f"(x)); return r;
}

// warp-sum, radix-8 then radix-4: two SHFL latencies on the chain (vs 5)
__device__ __forceinline__ float wsum32(float v) {
    float v1 = __shfl_xor_sync(0xffffffffu, v, 1);
    float v2 = __shfl_xor_sync(0xffffffffu, v, 2);
    float v3 = __shfl_xor_sync(0xffffffffu, v, 3);
    float v4 = __shfl_xor_sync(0xffffffffu, v, 4);
    float v5 = __shfl_xor_sync(0xffffffffu, v, 5);
    float v6 = __shfl_xor_sync(0xffffffffu, v, 6);
    float v7 = __shfl_xor_sync(0xffffffffu, v, 7);
    v = ((v + v1) + (v2 + v3)) + ((v4 + v5) + (v6 + v7));
    float u1 = __shfl_xor_sync(0xffffffffu, v, 8);
    float u2 = __shfl_xor_sync(0xffffffffu, v, 16);
    float u3 = __shfl_xor_sync(0xffffffffu, v, 24);
    return (v + u1) + (u2 + u3);
}

// ---------------------------------------------------------------------------
// Kernel 1: x_mean[b,s] = mean over D of x[b,s,:]   (one warp per row)
// ---------------------------------------------------------------------------
__global__ void __launch_bounds__(256) mean_kernel(const float* __restrict__ x) {
    int gw   = (blockIdx.x * 256 + threadIdx.x) >> 5;
    int lane = threadIdx.x & 31;
    const float4* xr = reinterpret_cast<const float4*>(x) + (size_t)gw * (DD / 4);
    float s = 0.f;
#pragma unroll
    for (int i = 0; i < 8; ++i) {
        float4 v = xr[i * 32 + lane];
        s += (v.x + v.y) + (v.z + v.w);
    }
#pragma unroll
    for (int o = 16; o > 0; o >>= 1) s += __shfl_xor_sync(0xffffffffu, s, o);
    if (lane == 0) g_xmean[gw] = s * (1.0f / DD);
}

// ---------------------------------------------------------------------------
// Kernel 2: sequential scan. One warp per batch, 8 states per lane (4 f32x2).
// Carried state is hn (pre-gate LN output); the gate is folded one step ahead
// into aeff = a∘sv and ceff = c∘sv (computed off the critical chain).
// Per-step critical chain:
//   FFMA2(hp) -> packed tree -> wsum32(s)||wsum32(q)
//   -> T=fma(q,256,-s^2) -> +eps -> RSQ -> rsw=r*w256 -> hn=FFMA2(hp,rsw,tmp)
// ys partials stored per-lane; cross-lane reduction deferred to ys_reduce.
// ---------------------------------------------------------------------------
__global__ void __launch_bounds__(32) scan_kernel(
    const float* __restrict__ vol,      // [B,S]
    const float* __restrict__ llr,      // [N]
    const float* __restrict__ logb,     // [N]
    const float* __restrict__ cvec,     // [N]
    const float* __restrict__ logstep,  // [1]
    const float* __restrict__ vgate,    // [N]
    const float* __restrict__ lnw,      // [N]
    const float* __restrict__ lnb)      // [N]
{
    __shared__ __align__(16) float sxm[SB + 8];
    __shared__ __align__(16) float svl[SB + 8];

    const int b    = blockIdx.x;
    const int lane = threadIdx.x;
    const float step = expf(logstep[0]);

    // packed per-pair constants: pair p holds states n0=p*64+lane, n1=n0+32
    u64 a2[4], bd2[4], g2[4], c2[4], w2[4], be2[4];   // w2 = 256*lnw
#pragma unroll
    for (int p = 0; p < 4; ++p) {
        int n0 = p * 64 + lane, n1 = n0 + 32;
        float lam0 = -expf(llr[n0]),  lam1 = -expf(llr[n1]);
        float ad0  = (2.f + step * lam0) / (2.f - step * lam0);
        float ad1  = (2.f + step * lam1) / (2.f - step * lam1);
        a2[p]  = pk2(ad0, ad1);
        bd2[p] = pk2(0.5f * step * (1.f + ad0) * expf(logb[n0]),
                     0.5f * step * (1.f + ad1) * expf(logb[n1]));
        g2[p]  = pk2(1.f / (1.f + expf(-vgate[n0])), 1.f / (1.f + expf(-vgate[n1])));
        c2[p]  = pk2(cvec[n0], cvec[n1]);
        w2[p]  = pk2(lnw[n0] * 256.f, lnw[n1] * 256.f);
        be2[p] = pk2(lnb[n0], lnb[n1]);
    }

    // preload xm/vol rows into shared memory (uniform LDS in the loop)
    const float* __restrict__ xmb = g_xmean + b * SB;
    const float* __restrict__ vlb = vol + b * SB;
#pragma unroll 4
    for (int i = lane; i < SB / 4; i += 32) {
        reinterpret_cast<float4*>(sxm)[i] = reinterpret_cast<const float4*>(xmb)[i];
        reinterpret_cast<float4*>(svl)[i] = reinterpret_cast<const float4*>(vlb)[i];
    }
    if (lane < 8) { sxm[SB + lane] = 0.f; svl[SB + lane] = 0.f; }
    __syncwarp();

    const u64 one2 = pk2(1.f, 1.f);

    // init pipeline for t=0
    float xm0 = sxm[0], vl0 = svl[0];
    u64 vl02 = pk2(vl0, vl0), xm02 = pk2(xm0, xm0);
    u64 ae_cur[4], ae_nxt[4], ce_cur[4], bdx[4], hn[4];
#pragma unroll
    for (int p = 0; p < 4; ++p) {
        u64 gv = f2fma(g2[p], vl02, one2);
        float glo, ghi; upk2(gv, glo, ghi);
        u64 sv = pk2(frcp(glo), frcp(ghi));       // 1/(1+g*vol_0)
        ce_cur[p] = f2mul(c2[p], sv);             // for ys at t=0
        ae_nxt[p] = f2mul(a2[p], sv);             // for recurrence at t=1
        ae_cur[p] = a2[p];                        // hn starts at 0 — value irrelevant
        bdx[p]    = f2mul(bd2[p], xm02);
        hn[p]     = pk2(0.f, 0.f);
    }

    float* __restrict__ partb = g_part + (size_t)b * SB * 32 + lane;

#pragma unroll 2
    for (int t = 0; t < SB; ++t) {
        float xm1 = sxm[t + 1], vl1 = svl[t + 1];

        // ---- critical path: hp = aeff*hn + bdx ----
        u64 hp0 = f2fma(ae_cur[0], hn[0], bdx[0]);
        u64 hp1 = f2fma(ae_cur[1], hn[1], bdx[1]);
        u64 hp2 = f2fma(ae_cur[2], hn[2], bdx[2]);
        u64 hp3 = f2fma(ae_cur[3], hn[3], bdx[3]);

        // packed local trees for s and q
        u64 s01 = f2add(hp0, hp1), s23 = f2add(hp2, hp3);
        u64 sal = f2add(s01, s23);
        float sl, sh; upk2(sal, sl, sh);
        float s = sl + sh;

        u64 q0 = f2mul(hp0, hp0), q1 = f2mul(hp1, hp1);
        u64 q2 = f2mul(hp2, hp2), q3 = f2mul(hp3, hp3);
        u64 qal = f2add(f2add(q0, q1), f2add(q2, q3));
        float ql, qh; upk2(qal, ql, qh);
        float q = ql + qh;

        s = wsum32(s);
        q = wsum32(q);

        // ---- off-chain: step t+1 aux (fills SHFL stall slots) ----
        u64 vl12 = pk2(vl1, vl1), xm12 = pk2(xm1, xm1);
        u64 ce_nn[4], ae_new[4], bdx_n[4];
#pragma unroll
        for (int p = 0; p < 4; ++p) {
            u64 gv = f2fma(g2[p], vl12, one2);
            float glo, ghi; upk2(gv, glo, ghi);
            u64 sv = pk2(frcp(glo), frcp(ghi));   // 1/(1+g*vol_{t+1})
            ce_nn[p] = f2mul(c2[p], sv);
            ae_new[p] = f2mul(a2[p], sv);
            bdx_n[p] = f2mul(bd2[p], xm12);
        }

        // ---- LN scalars: var*N^2 = q*N - s^2 ; rs_true = 256*rsq(T+eps*N^2) ----
        float T  = fmaf(q, 256.f, -s * s);
        float r  = frsq(T + 0.65536f);            // eps*N^2 = 1e-5*65536
        float sm = s * (-1.f / 256.f);
        float nsr = sm * r;                       // = -mu*rs_true / 256 (pairs with w2=256*lnw)
        u64 r2   = pk2(r, r);
        u64 nsr2 = pk2(nsr, nsr);

        u64 rsw0 = f2mul(r2, w2[0]), rsw1 = f2mul(r2, w2[1]);
        u64 rsw2 = f2mul(r2, w2[2]), rsw3 = f2mul(r2, w2[3]);
        u64 tp0 = f2fma(nsr2, w2[0], be2[0]);
        u64 tp1 = f2fma(nsr2, w2[1], be2[1]);
        u64 tp2 = f2fma(nsr2, w2[2], be2[2]);
        u64 tp3 = f2fma(nsr2, w2[3], be2[3]);

        hn[0] = f2fma(hp0, rsw0, tp0);            // <- carried state (chain end)
        hn[1] = f2fma(hp1, rsw1, tp1);
        hn[2] = f2fma(hp2, rsw2, tp2);
        hn[3] = f2fma(hp3, rsw3, tp3);

        // ys partial: p_lane = sum_k hn*ceff (gate folded into ceff)
        u64 pr = f2fma(hn[0], ce_cur[0],
                 f2fma(hn[1], ce_cur[1],
                 f2fma(hn[2], ce_cur[2],
                 f2mul(hn[3], ce_cur[3]))));
        float pl, ph; upk2(pr, pl, ph);
        partb[t * 32] = pl + ph;                  // coalesced 128B/warp store

        // rotate pipelines
#pragma unroll
        for (int p = 0; p < 4; ++p) {
            ae_cur[p] = ae_nxt[p];
            ae_nxt[p] = ae_new[p];
            ce_cur[p] = ce_nn[p];
            bdx[p]    = bdx_n[p];
        }
    }
}

// ---------------------------------------------------------------------------
// Kernel 2b: reduce 32 per-lane partials -> ys[b,s]   (one warp per row)
// ---------------------------------------------------------------------------
__global__ void __launch_bounds__(256) ys_reduce() {
    int gw   = (blockIdx.x * 256 + threadIdx.x) >> 5;
    int lane = threadIdx.x & 31;
    float v = g_part[(size_t)gw * 32 + lane];
#pragma unroll
    for (int o = 16; o > 0; o >>= 1) v += __shfl_xor_sync(0xffffffffu, v, o);
    if (lane == 0) g_ys[gw] = v;
}

// ---------------------------------------------------------------------------
// Kernel 3: out = (A + (1-A)*d) * x + (1-A) * ys[b,s]     (float4 vectorized)
// ---------------------------------------------------------------------------
__global__ void __launch_bounds__(256) out_kernel(
    const float* __restrict__ x, float* __restrict__ out,
    const float* __restrict__ log_d, const float* __restrict__ alpha)
{
    int i = blockIdx.x * 256 + threadIdx.x;
    float A  = 1.f / (1.f + expf(-alpha[0]));
    float cx = A + (1.f - A) * expf(log_d[0]);
    float cy = 1.f - A;
    float add = cy * g_ys[i >> 8];
    float4 v = reinterpret_cast<const float4*>(x)[i];
    v.x = fmaf(cx, v.x, add);
    v.y = fmaf(cx, v.y, add);
    v.z = fmaf(cx, v.z, add);
    v.w = fmaf(cx, v.w, add);
    reinterpret_cast<float4*>(out)[i] = v;
}

// ---------------------------------------------------------------------------
extern "C" void kernel_launch(void* const* d_in, const int* in_sizes, int n_in,
                              void* d_out, int out_size) {
    const float* x    = (const float*)d_in[0];   // [B,S,D]
    const float* vol  = (const float*)d_in[1];   // [B,S,1]
    const float* llr  = (const float*)d_in[2];   // [N]
    const float* logb = (const float*)d_in[3];   // [N,1]
    const float* cvec = (const float*)d_in[4];   // [1,N]
    const float* logd = (const float*)d_in[5];   // [1]
    const float* lstp = (const float*)d_in[6];   // [1]
    const float* vg   = (const float*)d_in[7];   // [N]
    const float* alp  = (const float*)d_in[8];   // [1]
    const float* lnw  = (const float*)d_in[9];   // [N]
    const float* lnb  = (const float*)d_in[10];  // [N]
    float* out = (float*)d_out;

    mean_kernel<<<(BB * SB) / 8, 256>>>(x);
    scan_kernel<<<BB, 32>>>(vol, llr, logb, cvec, lstp, vg, lnw, lnb);
    ys_reduce<<<(BB * SB) / 8, 256>>>();
    out_kernel<<<(BB * SB * DD) / 1024, 256>>>(x, out, logd, alp);
}

// round 7
// speedup vs baseline: 2.0134x; 1.2640x over previous
#include <cuda_runtime.h>

#define SB 4096
#define BB 8
#define DD 1024
#define NN 256

// scratch (device globals — no allocation allowed)
__device__ float g_xmean[BB * SB];
__device__ float g_part[BB * SB * 32];   // per-lane ys partials (reduced later)
__device__ float g_ys[BB * SB];

typedef unsigned long long u64;

// ---- packed f32x2 helpers (Blackwell FFMA2/FMUL2/FADD2) ----
__device__ __forceinline__ u64 pk2(float lo, float hi) {
    u64 r; asm("mov.b64 %0,{%1,%2};" : "=l"(r) : "f"(lo), "f"(hi)); return r;
}
__device__ __forceinline__ void upk2(u64 v, float& lo, float& hi) {
    asm("mov.b64 {%0,%1},%2;" : "=f"(lo), "=f"(hi) : "l"(v));
}
__device__ __forceinline__ u64 f2fma(u64 a, u64 b, u64 c) {
    u64 d; asm("fma.rn.f32x2 %0,%1,%2,%3;" : "=l"(d) : "l"(a), "l"(b), "l"(c)); return d;
}
__device__ __forceinline__ u64 f2mul(u64 a, u64 b) {
    u64 d; asm("mul.rn.f32x2 %0,%1,%2;" : "=l"(d) : "l"(a), "l"(b)); return d;
}
__device__ __forceinline__ u64 f2add(u64 a, u64 b) {
    u64 d; asm("add.rn.f32x2 %0,%1,%2;" : "=l"(d) : "l"(a), "l"(b)); return d;
}
__device__ __forceinline__ float frcp(float x) {
    float r; asm("rcp.approx.f32 %0,%1;" : "=f"(r) : "f"(x)); return r;
}
__device__ __forceinline__ float frsq(float x) {
    float r; asm("rsqrt.approx.f32 %0,%1;" : "=f"(r) : "f"(x)); return r;
}

// ---------------------------------------------------------------------------
// Kernel 1: x_mean[b,s] = mean over D of x[b,s,:]   (one warp per row)
// ---------------------------------------------------------------------------
__global__ void __launch_bounds__(256) mean_kernel(const float* __restrict__ x) {
    int gw   = (blockIdx.x * 256 + threadIdx.x) >> 5;
    int lane = threadIdx.x & 31;
    const float4* xr = reinterpret_cast<const float4*>(x) + (size_t)gw * (DD / 4);
    float s = 0.f;
#pragma unroll
    for (int i = 0; i < 8; ++i) {
        float4 v = xr[i * 32 + lane];
        s += (v.x + v.y) + (v.z + v.w);
    }
#pragma unroll
    for (int o = 16; o > 0; o >>= 1) s += __shfl_xor_sync(0xffffffffu, s, o);
    if (lane == 0) g_xmean[gw] = s * (1.0f / DD);
}

// ---------------------------------------------------------------------------
// Kernel 2: sequential scan. One warp per batch, 8 states per lane (4 f32x2).
// Carried state: hg = gated LN output. Per-step critical chain:
//   FFMA2(hp) -> packed q tree -> scale+F2I -> REDUX.S32 -> I2F
//   -> T -> RSQ -> z=FFMA2(hp,256r,-s*r) -> hn=FFMA2(z,w,b) -> hg=FMUL2(hn,sv)
// Fixed-point warp reduction: s*2^16, q*2^14 (worst-case |hp|<=17 => no ovf,
// quantization ~1e-5 rel on var, budget is 1e-3).
// ys partials stored per-lane; cross-lane reduction deferred to ys_reduce.
// ---------------------------------------------------------------------------
__global__ void __launch_bounds__(32) scan_kernel(
    const float* __restrict__ vol,      // [B,S]
    const float* __restrict__ llr,      // [N]
    const float* __restrict__ logb,     // [N]
    const float* __restrict__ cvec,     // [N]
    const float* __restrict__ logstep,  // [1]
    const float* __restrict__ vgate,    // [N]
    const float* __restrict__ lnw,      // [N]
    const float* __restrict__ lnb)      // [N]
{
    __shared__ __align__(16) float sxm[SB + 8];
    __shared__ __align__(16) float svl[SB + 8];

    const int b    = blockIdx.x;
    const int lane = threadIdx.x;
    const float step = expf(logstep[0]);

    // packed per-pair constants: pair p holds states n0=p*64+lane, n1=n0+32
    u64 a2[4], bd2[4], g2[4], c2[4], w2[4], be2[4];
#pragma unroll
    for (int p = 0; p < 4; ++p) {
        int n0 = p * 64 + lane, n1 = n0 + 32;
        float lam0 = -expf(llr[n0]),  lam1 = -expf(llr[n1]);
        float ad0  = (2.f + step * lam0) / (2.f - step * lam0);
        float ad1  = (2.f + step * lam1) / (2.f - step * lam1);
        a2[p]  = pk2(ad0, ad1);
        bd2[p] = pk2(0.5f * step * (1.f + ad0) * expf(logb[n0]),
                     0.5f * step * (1.f + ad1) * expf(logb[n1]));
        g2[p]  = pk2(1.f / (1.f + expf(-vgate[n0])), 1.f / (1.f + expf(-vgate[n1])));
        c2[p]  = pk2(cvec[n0], cvec[n1]);
        w2[p]  = pk2(lnw[n0], lnw[n1]);
        be2[p] = pk2(lnb[n0], lnb[n1]);
    }

    // preload xm/vol rows into shared memory (uniform LDS in the loop)
    const float* __restrict__ xmb = g_xmean + b * SB;
    const float* __restrict__ vlb = vol + b * SB;
#pragma unroll 4
    for (int i = lane; i < SB / 4; i += 32) {
        reinterpret_cast<float4*>(sxm)[i] = reinterpret_cast<const float4*>(xmb)[i];
        reinterpret_cast<float4*>(svl)[i] = reinterpret_cast<const float4*>(vlb)[i];
    }
    if (lane < 8) { sxm[SB + lane] = 0.f; svl[SB + lane] = 0.f; }
    __syncwarp();

    const u64 one2 = pk2(1.f, 1.f);

    // prime pipeline for t=0
    float xm0 = sxm[0], vl0 = svl[0];
    u64 xm02 = pk2(xm0, xm0), vl02 = pk2(vl0, vl0);
    u64 sv[4], bdx[4], hg[4];
#pragma unroll
    for (int p = 0; p < 4; ++p) {
        u64 gv = f2fma(g2[p], vl02, one2);
        float glo, ghi; upk2(gv, glo, ghi);
        sv[p]  = pk2(frcp(glo), frcp(ghi));       // 1/(1+g*vol_0)
        bdx[p] = f2mul(bd2[p], xm02);
        hg[p]  = pk2(0.f, 0.f);
    }

    float* __restrict__ partb = g_part + (size_t)b * SB * 32 + lane;

#pragma unroll 2
    for (int t = 0; t < SB; ++t) {
        float xm1 = sxm[t + 1], vl1 = svl[t + 1];

        // ---- critical path: hp = a*hg + bdx ----
        u64 hp0 = f2fma(a2[0], hg[0], bdx[0]);
        u64 hp1 = f2fma(a2[1], hg[1], bdx[1]);
        u64 hp2 = f2fma(a2[2], hg[2], bdx[2]);
        u64 hp3 = f2fma(a2[3], hg[3], bdx[3]);

        // packed local trees
        u64 sal = f2add(f2add(hp0, hp1), f2add(hp2, hp3));
        float sl, sh; upk2(sal, sl, sh);
        float s = sl + sh;
        u64 qal = f2fma(hp3, hp3, f2fma(hp2, hp2, f2fma(hp1, hp1, f2mul(hp0, hp0))));
        float ql, qh; upk2(qal, ql, qh);
        float q = ql + qh;

        // fixed-point warp reduction: one REDUX each (replaces 5-level SHFL)
        int Si = __float2int_rn(s * 65536.f);
        int Qi = __float2int_rn(q * 16384.f);
        Si = __reduce_add_sync(0xffffffffu, Si);
        Qi = __reduce_add_sync(0xffffffffu, Qi);
        float Sf = __int2float_rn(Si);            // = s_tot * 2^16
        float Qf = __int2float_rn(Qi);            // = q_tot * 2^14

        // ---- off-chain: step t+1 aux (fills REDUX latency) ----
        u64 xm12 = pk2(xm1, xm1), vl12 = pk2(vl1, vl1);
        u64 svn[4], bdxn[4];
#pragma unroll
        for (int p = 0; p < 4; ++p) {
            u64 gv = f2fma(g2[p], vl12, one2);
            float glo, ghi; upk2(gv, glo, ghi);
            svn[p]  = pk2(frcp(glo), frcp(ghi));  // 1/(1+g*vol_{t+1})
            bdxn[p] = f2mul(bd2[p], xm12);
        }

        // ---- LN scalars ----
        // T = q*256 - s^2 + eps*N^2 = Qf*2^-6 - (Sf*2^-16)^2 + 0.65536
        float s32 = Sf * 2.3283064365386963e-10f;     // Sf * 2^-32
        float sq  = fmaf(-s32, Sf, 0.65536f);
        float T   = fmaf(Qf, 0.015625f, sq);
        float r   = frsq(T);                          // rs_true = 256*r
        float r256 = r * 256.f;
        float nsr  = (Sf * -1.52587890625e-05f) * r;  // -s*r = -mu*rs_true
        u64 r2 = pk2(r256, r256), n2 = pk2(nsr, nsr);

        // hn = ((hp - mu)*rs)*w + b  ;  hg = hn * sv   (carried state)
        u64 z0 = f2fma(hp0, r2, n2), z1 = f2fma(hp1, r2, n2);
        u64 z2 = f2fma(hp2, r2, n2), z3 = f2fma(hp3, r2, n2);
        u64 hn0 = f2fma(z0, w2[0], be2[0]);
        u64 hn1 = f2fma(z1, w2[1], be2[1]);
        u64 hn2 = f2fma(z2, w2[2], be2[2]);
        u64 hn3 = f2fma(z3, w2[3], be2[3]);
        hg[0] = f2mul(hn0, sv[0]);
        hg[1] = f2mul(hn1, sv[1]);
        hg[2] = f2mul(hn2, sv[2]);
        hg[3] = f2mul(hn3, sv[3]);

        // ys partial (off critical chain; only feeds the store)
        u64 pr = f2fma(hg[0], c2[0],
                 f2fma(hg[1], c2[1],
                 f2fma(hg[2], c2[2],
                 f2mul(hg[3], c2[3]))));
        float pl, ph; upk2(pr, pl, ph);
        partb[t * 32] = pl + ph;                  // coalesced 128B/warp store

        // rotate pipelines
#pragma unroll
        for (int p = 0; p < 4; ++p) { sv[p] = svn[p]; bdx[p] = bdxn[p]; }
    }
}

// ---------------------------------------------------------------------------
// Kernel 2b: reduce 32 per-lane partials -> ys[b,s]   (one warp per row)
// ---------------------------------------------------------------------------
__global__ void __launch_bounds__(256) ys_reduce() {
    int gw   = (blockIdx.x * 256 + threadIdx.x) >> 5;
    int lane = threadIdx.x & 31;
    float v = g_part[(size_t)gw * 32 + lane];
#pragma unroll
    for (int o = 16; o > 0; o >>= 1) v += __shfl_xor_sync(0xffffffffu, v, o);
    if (lane == 0) g_ys[gw] = v;
}

// ---------------------------------------------------------------------------
// Kernel 3: out = (A + (1-A)*d) * x + (1-A) * ys[b,s]     (float4 vectorized)
// ---------------------------------------------------------------------------
__global__ void __launch_bounds__(256) out_kernel(
    const float* __restrict__ x, float* __restrict__ out,
    const float* __restrict__ log_d, const float* __restrict__ alpha)
{
    int i = blockIdx.x * 256 + threadIdx.x;
    float A  = 1.f / (1.f + expf(-alpha[0]));
    float cx = A + (1.f - A) * expf(log_d[0]);
    float cy = 1.f - A;
    float add = cy * g_ys[i >> 8];
    float4 v = reinterpret_cast<const float4*>(x)[i];
    v.x = fmaf(cx, v.x, add);
    v.y = fmaf(cx, v.y, add);
    v.z = fmaf(cx, v.z, add);
    v.w = fmaf(cx, v.w, add);
    reinterpret_cast<float4*>(out)[i] = v;
}

// ---------------------------------------------------------------------------
extern "C" void kernel_launch(void* const* d_in, const int* in_sizes, int n_in,
                              void* d_out, int out_size) {
    const float* x    = (const float*)d_in[0];   // [B,S,D]
    const float* vol  = (const float*)d_in[1];   // [B,S,1]
    const float* llr  = (const float*)d_in[2];   // [N]
    const float* logb = (const float*)d_in[3];   // [N,1]
    const float* cvec = (const float*)d_in[4];   // [1,N]
    const float* logd = (const float*)d_in[5];   // [1]
    const float* lstp = (const float*)d_in[6];   // [1]
    const float* vg   = (const float*)d_in[7];   // [N]
    const float* alp  = (const float*)d_in[8];   // [1]
    const float* lnw  = (const float*)d_in[9];   // [N]
    const float* lnb  = (const float*)d_in[10];  // [N]
    float* out = (float*)d_out;

    mean_kernel<<<(BB * SB) / 8, 256>>>(x);
    scan_kernel<<<BB, 32>>>(vol, llr, logb, cvec, lstp, vg, lnw, lnb);
    ys_reduce<<<(BB * SB) / 8, 256>>>();
    out_kernel<<<(BB * SB * DD) / 1024, 256>>>(x, out, logd, alp);
}

// round 11
// speedup vs baseline: 2.1779x; 1.0817x over previous
#include <cuda_runtime.h>

#define SB 4096
#define BB 8
#define DD 1024
#define NN 256

// scratch (device globals — no allocation allowed)
__device__ float g_xmean[BB * SB];
__device__ float g_part[BB * SB * 32];   // per-lane ys partials (reduced later)
__device__ float g_ys[BB * SB];

typedef unsigned long long u64;

// ---- packed f32x2 helpers (Blackwell FFMA2/FMUL2/FADD2) ----
__device__ __forceinline__ u64 pk2(float lo, float hi) {
    u64 r; asm("mov.b64 %0,{%1,%2};" : "=l"(r) : "f"(lo), "f"(hi)); return r;
}
__device__ __forceinline__ void upk2(u64 v, float& lo, float& hi) {
    asm("mov.b64 {%0,%1},%2;" : "=f"(lo), "=f"(hi) : "l"(v));
}
__device__ __forceinline__ u64 f2fma(u64 a, u64 b, u64 c) {
    u64 d; asm("fma.rn.f32x2 %0,%1,%2,%3;" : "=l"(d) : "l"(a), "l"(b), "l"(c)); return d;
}
__device__ __forceinline__ u64 f2mul(u64 a, u64 b) {
    u64 d; asm("mul.rn.f32x2 %0,%1,%2;" : "=l"(d) : "l"(a), "l"(b)); return d;
}
__device__ __forceinline__ u64 f2add(u64 a, u64 b) {
    u64 d; asm("add.rn.f32x2 %0,%1,%2;" : "=l"(d) : "l"(a), "l"(b)); return d;
}
__device__ __forceinline__ float frcp(float x) {
    float r; asm("rcp.approx.f32 %0,%1;" : "=f"(r) : "f"(x)); return r;
}
__device__ __forceinline__ float frsq(float x) {
    float r; asm("rsqrt.approx.f32 %0,%1;" : "=f"(r) : "f"(x)); return r;
}

// ---------------------------------------------------------------------------
// Kernel 1: x_mean[b,s] = mean over D of x[b,s,:]   (one warp per row)
// ---------------------------------------------------------------------------
__global__ void __launch_bounds__(256) mean_kernel(const float* __restrict__ x) {
    int gw   = (blockIdx.x * 256 + threadIdx.x) >> 5;
    int lane = threadIdx.x & 31;
    const float4* xr = reinterpret_cast<const float4*>(x) + (size_t)gw * (DD / 4);
    float s = 0.f;
#pragma unroll
    for (int i = 0; i < 8; ++i) {
        float4 v = xr[i * 32 + lane];
        s += (v.x + v.y) + (v.z + v.w);
    }
#pragma unroll
    for (int o = 16; o > 0; o >>= 1) s += __shfl_xor_sync(0xffffffffu, s, o);
    if (lane == 0) g_xmean[gw] = s * (1.0f / DD);
}

// ---------------------------------------------------------------------------
// Kernel 2: sequential scan. One warp per batch, 8 states per lane (4 f32x2).
// Carried state: hg (gated LN output). Per-step critical chain:
//   FFMA2(hp) -> q tree -> F2I -> REDUX.S32 -> I2F -> T fma -> RSQ
//   -> hg = FFMA2(dwsv, r, besv)        (d, dwsv computed parallel to RSQ)
// Per-step gate folding happens OFF-chain one step ahead:
//   wsv = 256*w o sv_{t+1},  besv = be o sv_{t+1},  bdx = bd*xm_{t+1}
// MUFU ORDER MATTERS (in-order warp, rt=8): RSQ issues first, the 8 RCPs for
// t+1 issue last so their 64-cyc MUFU drain overlaps the next step's front.
// ---------------------------------------------------------------------------
__global__ void __launch_bounds__(32) scan_kernel(
    const float* __restrict__ vol,      // [B,S]
    const float* __restrict__ llr,      // [N]
    const float* __restrict__ logb,     // [N]
    const float* __restrict__ cvec,     // [N]
    const float* __restrict__ logstep,  // [1]
    const float* __restrict__ vgate,    // [N]
    const float* __restrict__ lnw,      // [N]
    const float* __restrict__ lnb)      // [N]
{
    __shared__ __align__(16) float sxm[SB + 8];
    __shared__ __align__(16) float svl[SB + 8];

    const int b    = blockIdx.x;
    const int lane = threadIdx.x;
    const float step = expf(logstep[0]);

    // packed per-pair constants: pair p holds states n0=p*64+lane, n1=n0+32
    u64 a2[4], bd2[4], g2[4], c2[4], w2[4], be2[4];   // w2 = 256*lnw
#pragma unroll
    for (int p = 0; p < 4; ++p) {
        int n0 = p * 64 + lane, n1 = n0 + 32;
        float lam0 = -expf(llr[n0]),  lam1 = -expf(llr[n1]);
        float ad0  = (2.f + step * lam0) / (2.f - step * lam0);
        float ad1  = (2.f + step * lam1) / (2.f - step * lam1);
        a2[p]  = pk2(ad0, ad1);
        bd2[p] = pk2(0.5f * step * (1.f + ad0) * expf(logb[n0]),
                     0.5f * step * (1.f + ad1) * expf(logb[n1]));
        g2[p]  = pk2(1.f / (1.f + expf(-vgate[n0])), 1.f / (1.f + expf(-vgate[n1])));
        c2[p]  = pk2(cvec[n0], cvec[n1]);
        w2[p]  = pk2(lnw[n0] * 256.f, lnw[n1] * 256.f);
        be2[p] = pk2(lnb[n0], lnb[n1]);
    }

    // preload xm/vol rows into shared memory (uniform LDS in the loop)
    const float* __restrict__ xmb = g_xmean + b * SB;
    const float* __restrict__ vlb = vol + b * SB;
#pragma unroll 4
    for (int i = lane; i < SB / 4; i += 32) {
        reinterpret_cast<float4*>(sxm)[i] = reinterpret_cast<const float4*>(xmb)[i];
        reinterpret_cast<float4*>(svl)[i] = reinterpret_cast<const float4*>(vlb)[i];
    }
    if (lane < 8) { sxm[SB + lane] = 0.f; svl[SB + lane] = 0.f; }
    __syncwarp();

    const u64 one2 = pk2(1.f, 1.f);

    // prime pipeline for t=0: wsv/besv/bdx from vol[0], xm[0]
    float xm0 = sxm[0], vl0 = svl[0];
    u64 xm02 = pk2(xm0, xm0), vl02 = pk2(vl0, vl0);
    u64 wsv[4], besv[4], bdx[4], hg[4];
#pragma unroll
    for (int p = 0; p < 4; ++p) {
        u64 gv = f2fma(g2[p], vl02, one2);
        float glo, ghi; upk2(gv, glo, ghi);
        u64 sv  = pk2(frcp(glo), frcp(ghi));     // 1/(1+g*vol_0)
        wsv[p]  = f2mul(w2[p], sv);              // 256*w o sv
        besv[p] = f2mul(be2[p], sv);
        bdx[p]  = f2mul(bd2[p], xm02);
        hg[p]   = pk2(0.f, 0.f);
    }

    float* __restrict__ partb = g_part + (size_t)b * SB * 32 + lane;

#pragma unroll 2
    for (int t = 0; t < SB; ++t) {
        float xm1 = sxm[t + 1], vl1 = svl[t + 1];

        // ---- critical chain: hp = a*hg + bdx ----
        u64 hp0 = f2fma(a2[0], hg[0], bdx[0]);
        u64 hp1 = f2fma(a2[1], hg[1], bdx[1]);
        u64 hp2 = f2fma(a2[2], hg[2], bdx[2]);
        u64 hp3 = f2fma(a2[3], hg[3], bdx[3]);

        // local trees (tree form, not serial fma chain)
        u64 sal = f2add(f2add(hp0, hp1), f2add(hp2, hp3));
        float sl, sh; upk2(sal, sl, sh);
        float s = sl + sh;
        u64 qq0 = f2mul(hp0, hp0), qq1 = f2mul(hp1, hp1);
        u64 qq2 = f2mul(hp2, hp2), qq3 = f2mul(hp3, hp3);
        u64 qal = f2add(f2add(qq0, qq1), f2add(qq2, qq3));
        float ql, qh; upk2(qal, ql, qh);
        float q = ql + qh;

        // fixed-point warp reduction (one REDUX each)
        int Si = __float2int_rn(s * 65536.f);
        int Qi = __float2int_rn(q * 16384.f);
        Si = __reduce_add_sync(0xffffffffu, Si);
        Qi = __reduce_add_sync(0xffffffffu, Qi);
        float Sf = __int2float_rn(Si);            // = s_tot * 2^16
        float Qf = __int2float_rn(Qi);            // = q_tot * 2^14

        // T = N^2*(var+eps) = q*256 - s^2 + 0.65536 (in scaled domain)
        float s32 = Sf * 2.3283064365386963e-10f;     // Sf * 2^-32
        float sq  = fmaf(-s32, Sf, 0.65536f);
        float T   = fmaf(Qf, 0.015625f, sq);
        float r   = frsq(T);                          // rs_true = 256*r (256 folded in wsv)

        // d = hp - mu ; dwsv = d o wsv  — both independent of RSQ result,
        // issue while RSQ computes
        float nm = Sf * -5.9604644775390625e-08f;     // -mu = -Sf*2^-16/256
        u64 nm2 = pk2(nm, nm);
        u64 d0 = f2add(hp0, nm2), d1 = f2add(hp1, nm2);
        u64 d2 = f2add(hp2, nm2), d3 = f2add(hp3, nm2);
        u64 dw0 = f2mul(d0, wsv[0]), dw1 = f2mul(d1, wsv[1]);
        u64 dw2 = f2mul(d2, wsv[2]), dw3 = f2mul(d3, wsv[3]);

        u64 r2 = pk2(r, r);
        hg[0] = f2fma(dw0, r2, besv[0]);          // <- carried state (chain end)
        hg[1] = f2fma(dw1, r2, besv[1]);
        hg[2] = f2fma(dw2, r2, besv[2]);
        hg[3] = f2fma(dw3, r2, besv[3]);

        // ---- off-chain for t+1: RCPs issue AFTER this step's RSQ so the
        // MUFU drain (8 x rt=8) overlaps the next step's front ----
        u64 xm12 = pk2(xm1, xm1), vl12 = pk2(vl1, vl1);
#pragma unroll
        for (int p = 0; p < 4; ++p) {
            u64 gv = f2fma(g2[p], vl12, one2);
            float glo, ghi; upk2(gv, glo, ghi);
            u64 sv  = pk2(frcp(glo), frcp(ghi));  // 1/(1+g*vol_{t+1})
            wsv[p]  = f2mul(w2[p], sv);
            besv[p] = f2mul(be2[p], sv);
            bdx[p]  = f2mul(bd2[p], xm12);
        }

        // ys partial (off critical chain; only feeds the store)
        u64 pr = f2fma(hg[0], c2[0],
                 f2fma(hg[1], c2[1],
                 f2fma(hg[2], c2[2],
                 f2mul(hg[3], c2[3]))));
        float pl, ph; upk2(pr, pl, ph);
        partb[t * 32] = pl + ph;                  // coalesced 128B/warp store
    }
}

// ---------------------------------------------------------------------------
// Kernel 2b: reduce 32 per-lane partials -> ys[b,s]   (one warp per row)
// ---------------------------------------------------------------------------
__global__ void __launch_bounds__(256) ys_reduce() {
    int gw   = (blockIdx.x * 256 + threadIdx.x) >> 5;
    int lane = threadIdx.x & 31;
    float v = g_part[(size_t)gw * 32 + lane];
#pragma unroll
    for (int o = 16; o > 0; o >>= 1) v += __shfl_xor_sync(0xffffffffu, v, o);
    if (lane == 0) g_ys[gw] = v;
}

// ---------------------------------------------------------------------------
// Kernel 3: out = (A + (1-A)*d) * x + (1-A) * ys[b,s]     (float4 vectorized)
// ---------------------------------------------------------------------------
__global__ void __launch_bounds__(256) out_kernel(
    const float* __restrict__ x, float* __restrict__ out,
    const float* __restrict__ log_d, const float* __restrict__ alpha)
{
    int i = blockIdx.x * 256 + threadIdx.x;
    float A  = 1.f / (1.f + expf(-alpha[0]));
    float cx = A + (1.f - A) * expf(log_d[0]);
    float cy = 1.f - A;
    float add = cy * g_ys[i >> 8];
    float4 v = reinterpret_cast<const float4*>(x)[i];
    v.x = fmaf(cx, v.x, add);
    v.y = fmaf(cx, v.y, add);
    v.z = fmaf(cx, v.z, add);
    v.w = fmaf(cx, v.w, add);
    reinterpret_cast<float4*>(out)[i] = v;
}

// ---------------------------------------------------------------------------
extern "C" void kernel_launch(void* const* d_in, const int* in_sizes, int n_in,
                              void* d_out, int out_size) {
    const float* x    = (const float*)d_in[0];   // [B,S,D]
    const float* vol  = (const float*)d_in[1];   // [B,S,1]
    const float* llr  = (const float*)d_in[2];   // [N]
    const float* logb = (const float*)d_in[3];   // [N,1]
    const float* cvec = (const float*)d_in[4];   // [1,N]
    const float* logd = (const float*)d_in[5];   // [1]
    const float* lstp = (const float*)d_in[6];   // [1]
    const float* vg   = (const float*)d_in[7];   // [N]
    const float* alp  = (const float*)d_in[8];   // [1]
    const float* lnw  = (const float*)d_in[9];   // [N]
    const float* lnb  = (const float*)d_in[10];  // [N]
    float* out = (float*)d_out;

    mean_kernel<<<(BB * SB) / 8, 256>>>(x);
    scan_kernel<<<BB, 32>>>(vol, llr, logb, cvec, lstp, vg, lnw, lnb);
    ys_reduce<<<(BB * SB) / 8, 256>>>();
    out_kernel<<<(BB * SB * DD) / 1024, 256>>>(x, out, logd, alp);
}